// round 1
// baseline (speedup 1.0000x reference)
#include <cuda_runtime.h>

#define Nn   128
#define Hh   2
#define Ll   1024
#define Cc   (Hh * Ll)      /* 2048 columns = h*L flattened */
#define PRED (Nn * Cc)      /* 262144 */

#define SA_LD 132           /* padded lead dim for Amat tile (32 x 128) */
#define SB_LD 68            /* padded lead dim for alpha tile (128 x 64) */

__device__ float g_alpha[PRED];
__device__ float g_Ss[PRED];

// ---------------------------------------------------------------------------
// Kernel 1: per-(n,h)-row fused relu + cumsum + exponential-decay recurrence.
// 256 blocks (one per row), 128 threads, 8 contiguous elements per thread.
// Is[i] = d*Is[i-1] + s[i]  solved with a weighted Kogge-Stone scan (ratio d^8
// across threads, d^256 across warps).
// ---------------------------------------------------------------------------
__global__ void __launch_bounds__(128) scan_kernel(const float* __restrict__ x,
                                                   const float* __restrict__ taus,
                                                   const float* __restrict__ r0dt,
                                                   float* __restrict__ out)
{
    int row  = blockIdx.x;          // n*H + h
    int t    = threadIdx.x;         // 0..127
    int lane = t & 31, wid = t >> 5;
    int base = row * Ll + t * 8;

    const float4* xv = reinterpret_cast<const float4*>(x + base);
    float4 v0 = xv[0], v1 = xv[1];
    float s[8] = { fmaxf(v0.x, 0.f), fmaxf(v0.y, 0.f), fmaxf(v0.z, 0.f), fmaxf(v0.w, 0.f),
                   fmaxf(v1.x, 0.f), fmaxf(v1.y, 0.f), fmaxf(v1.z, 0.f), fmaxf(v1.w, 0.f) };

    float tau = taus[row];
    float R0  = r0dt[row];
    float d   = 1.f - 1.f / tau;

    // pass 1: zero-seeded local carries for this 8-element chunk
    float cum = 0.f, isv = 0.f;
#pragma unroll
    for (int k = 0; k < 8; k++) { cum += s[k]; isv = fmaf(d, isv, s[k]); }

    float d2 = d * d, d4 = d2 * d2, r8 = d4 * d4;   // d^8

    // warp-level inclusive scans: plain sum (cum) and ratio-r8 recurrence (is)
    float inclI = isv, inclC = cum, rp = r8;
#pragma unroll
    for (int off = 1; off < 32; off <<= 1) {
        float ui = __shfl_up_sync(0xffffffffu, inclI, off);
        float uc = __shfl_up_sync(0xffffffffu, inclC, off);
        if (lane >= off) { inclI = fmaf(rp, ui, inclI); inclC += uc; }
        rp *= rp;                                   // r8^(2^step)
    }

    __shared__ float wI[4], wC[4];
    if (lane == 31) { wI[wid] = inclI; wC[wid] = inclC; }
    __syncthreads();

    float Rw = rp;                                  // r8^32 = d^256 (per-warp ratio)
    float exI = 0.f, exC = 0.f, aI = 0.f, aC = 0.f;
#pragma unroll
    for (int w = 0; w < 4; w++) {
        if (w == wid) { exI = aI; exC = aC; }       // exclusive warp carries
        aI = fmaf(Rw, aI, wI[w]);
        aC += wC[w];
    }

    float upI = __shfl_up_sync(0xffffffffu, inclI, 1);
    float upC = __shfl_up_sync(0xffffffffu, inclC, 1);
    if (lane == 0) { upI = 0.f; upC = 0.f; }
    float XI = fmaf(exI, __powf(r8, (float)lane), upI);   // Is at element 8t-1
    float XC = upC + exC;                                  // cumsum through 8t-1

    // pass 2: rerun local recurrences seeded with exclusive carries
    float al[8], ss[8];
    float ci = XI, cc = XC;
#pragma unroll
    for (int k = 0; k < 8; k++) {
        ci = fmaf(d, ci, s[k]);
        cc += s[k];
        al[k] = 1.f - __expf(-R0 * ci);
        ss[k] = 1.f - cc;
    }

    float4* ga = reinterpret_cast<float4*>(g_alpha + base);
    ga[0] = make_float4(al[0], al[1], al[2], al[3]);
    ga[1] = make_float4(al[4], al[5], al[6], al[7]);
    float4* gs = reinterpret_cast<float4*>(g_Ss + base);
    gs[0] = make_float4(ss[0], ss[1], ss[2], ss[3]);
    gs[1] = make_float4(ss[4], ss[5], ss[6], ss[7]);
    float4* go = reinterpret_cast<float4*>(out + PRED + base);   // signal output
    go[0] = make_float4(s[0], s[1], s[2], s[3]);
    go[1] = make_float4(s[4], s[5], s[6], s[7]);
}

// ---------------------------------------------------------------------------
// Kernel 2: Alpha = alpha + Amat @ alpha ;  pred = Alpha * Ss ; plus Amat + I.
// Grid (32 col-tiles x 4 row-tiles); block tile 32 rows x 64 cols; thread
// tile 2x4. Whole m-dimension (128) cached in smem in one shot.
// ---------------------------------------------------------------------------
__global__ void __launch_bounds__(256) gemm_kernel(const float* __restrict__ Amat,
                                                   float* __restrict__ out)
{
    extern __shared__ float sm[];
    float* sA = sm;                  // [32][SA_LD]: rows k0..k0+31, all 128 m
    float* sB = sm + 32 * SA_LD;     // [128][SB_LD]: all m, 64 local cols

    int bx = blockIdx.x;             // 64-col tile
    int by = blockIdx.y;             // 32-row tile
    int tid = threadIdx.x;
    int k0 = by * 32, c0 = bx * 64;

#pragma unroll
    for (int i = tid; i < 32 * 128; i += 256) {
        int k = i >> 7, m = i & 127;
        sA[k * SA_LD + m] = Amat[(k0 + k) * 128 + m];
    }
#pragma unroll
    for (int i = tid; i < 128 * 16; i += 256) {
        int m = i >> 4, cq = i & 15;
        float4 v = *reinterpret_cast<const float4*>(&g_alpha[m * Cc + c0 + cq * 4]);
        *reinterpret_cast<float4*>(&sB[m * SB_LD + cq * 4]) = v;
    }
    __syncthreads();

    int tx = tid & 15;               // col quad: local cols tx*4 .. +3
    int ty = tid >> 4;               // row pair: local rows 2*ty, 2*ty+1
    int kr = 2 * ty;
    int cl = tx * 4;

    // identity term: Alpha = alpha + Amat@alpha  (row k0+kr lives in sB too)
    float4 i0 = *reinterpret_cast<float4*>(&sB[(k0 + kr)     * SB_LD + cl]);
    float4 i1 = *reinterpret_cast<float4*>(&sB[(k0 + kr + 1) * SB_LD + cl]);
    float acc0[4] = { i0.x, i0.y, i0.z, i0.w };
    float acc1[4] = { i1.x, i1.y, i1.z, i1.w };

#pragma unroll 8
    for (int m = 0; m < 128; m++) {
        float4 bv = *reinterpret_cast<float4*>(&sB[m * SB_LD + cl]);
        float a0 = sA[kr * SA_LD + m];
        float a1 = sA[(kr + 1) * SA_LD + m];
        acc0[0] = fmaf(a0, bv.x, acc0[0]);
        acc0[1] = fmaf(a0, bv.y, acc0[1]);
        acc0[2] = fmaf(a0, bv.z, acc0[2]);
        acc0[3] = fmaf(a0, bv.w, acc0[3]);
        acc1[0] = fmaf(a1, bv.x, acc1[0]);
        acc1[1] = fmaf(a1, bv.y, acc1[1]);
        acc1[2] = fmaf(a1, bv.z, acc1[2]);
        acc1[3] = fmaf(a1, bv.w, acc1[3]);
    }

    int gk0 = k0 + kr;
    const float4 ss0 = *reinterpret_cast<const float4*>(&g_Ss[gk0 * Cc + c0 + cl]);
    const float4 ss1 = *reinterpret_cast<const float4*>(&g_Ss[(gk0 + 1) * Cc + c0 + cl]);
    float4 o0 = make_float4(acc0[0] * ss0.x, acc0[1] * ss0.y, acc0[2] * ss0.z, acc0[3] * ss0.w);
    float4 o1 = make_float4(acc1[0] * ss1.x, acc1[1] * ss1.y, acc1[2] * ss1.z, acc1[3] * ss1.w);
    *reinterpret_cast<float4*>(&out[gk0 * Cc + c0 + cl])       = o0;
    *reinterpret_cast<float4*>(&out[(gk0 + 1) * Cc + c0 + cl]) = o1;

    // third output: tempAmat.T = Amat + I  (128 blocks x 128 elements)
    int lb = by * 32 + bx;           // 0..127 -> row of the 128x128 output
    if (tid < 128) {
        int idx = lb * 128 + tid;
        out[2 * PRED + idx] = Amat[idx] + (lb == tid ? 1.f : 0.f);
    }
}

extern "C" void kernel_launch(void* const* d_in, const int* in_sizes, int n_in,
                              void* d_out, int out_size)
{
    const float* x    = (const float*)d_in[0];
    const float* Amat = (const float*)d_in[1];
    const float* taus = (const float*)d_in[2];
    const float* r0   = (const float*)d_in[3];
    float* out = (float*)d_out;

    (void)in_sizes; (void)n_in; (void)out_size;

    size_t smem = (32 * SA_LD + 128 * SB_LD) * sizeof(float);  // ~51.7 KB
    cudaFuncSetAttribute(gemm_kernel, cudaFuncAttributeMaxDynamicSharedMemorySize, (int)smem);

    scan_kernel<<<Nn * Hh, 128>>>(x, taus, r0, out);
    gemm_kernel<<<dim3(32, 4), 256, smem>>>(Amat, out);
}